// round 1
// baseline (speedup 1.0000x reference)
#include <cuda_runtime.h>
#include <math.h>

#define DIM 384
#define NH 6
#define DH 64
#define BATCH 8
#define SEQ 1024

// Scratch (no device allocation allowed -> __device__ globals)
__device__ float g_q [BATCH*NH*SEQ*DH];
__device__ float g_k [BATCH*NH*SEQ*DH];
__device__ float g_v [BATCH*NH*SEQ*DH];
__device__ float g_ao[BATCH*SEQ*DIM];
__device__ float g_pl[SEQ*SEQ];

// ---------------------------------------------------------------------------
// Positional kernel: g_pl[i][j] = (1-lam) * exp(-dist2(i,j) / (2 sigma^2))
// ---------------------------------------------------------------------------
__global__ void pos_kernel(const float* __restrict__ logit_lambda,
                           const float* __restrict__ log_sigma)
{
    float ls  = log_sigma[0];
    float sig = log1pf(expf(ls)) + 1e-6f;          // softplus + eps
    float inv = 1.0f / (2.0f * sig * sig);
    float lam = 1.0f / (1.0f + expf(-logit_lambda[0]));
    float oml = 1.0f - lam;

    int i = blockIdx.x;
    float yi = (float)(i >> 5), xi = (float)(i & 31);
    for (int j = threadIdx.x; j < SEQ; j += blockDim.x) {
        float yj = (float)(j >> 5), xj = (float)(j & 31);
        float dy = yi - yj, dx = xi - xj;
        g_pl[i*SEQ + j] = oml * __expf(-(dy*dy + dx*dx) * inv);
    }
}

// ---------------------------------------------------------------------------
// Fused QKV GEMM: Y = X @ W^T, written in (b, h, n, dh) layout.
// 128x128 tile, BK=16, k-transposed SMEM, 8x8 micro-tile per thread.
// ---------------------------------------------------------------------------
__global__ void __launch_bounds__(256) gemm_qkv(
    const float* __restrict__ X,
    const float* __restrict__ Wq,
    const float* __restrict__ Wk,
    const float* __restrict__ Wv)
{
    const float* W = (blockIdx.z == 0) ? Wq : (blockIdx.z == 1 ? Wk : Wv);
    float* Y       = (blockIdx.z == 0) ? g_q : (blockIdx.z == 1 ? g_k : g_v);

    __shared__ float AsT[16][128];
    __shared__ float BsT[16][128];

    int tid = threadIdx.x;
    int tx = tid & 15, ty = tid >> 4;
    int m0 = blockIdx.x * 128, n0 = blockIdx.y * 128;

    float acc[8][8] = {};

    for (int k0 = 0; k0 < DIM; k0 += 16) {
        #pragma unroll
        for (int u = 0; u < 2; u++) {
            int idx = u*256 + tid;            // float4 index in 128x16 tile
            int m = idx >> 2, kc = (idx & 3) << 2;
            float4 va = *(const float4*)(X + (size_t)(m0+m)*DIM + k0 + kc);
            AsT[kc  ][m] = va.x; AsT[kc+1][m] = va.y;
            AsT[kc+2][m] = va.z; AsT[kc+3][m] = va.w;
            float4 vb = *(const float4*)(W + (size_t)(n0+m)*DIM + k0 + kc);
            BsT[kc  ][m] = vb.x; BsT[kc+1][m] = vb.y;
            BsT[kc+2][m] = vb.z; BsT[kc+3][m] = vb.w;
        }
        __syncthreads();
        #pragma unroll
        for (int kk = 0; kk < 16; kk++) {
            float a[8], b[8];
            *(float4*)(a  ) = *(const float4*)&AsT[kk][ty*8];
            *(float4*)(a+4) = *(const float4*)&AsT[kk][ty*8+4];
            *(float4*)(b  ) = *(const float4*)&BsT[kk][tx*8];
            *(float4*)(b+4) = *(const float4*)&BsT[kk][tx*8+4];
            #pragma unroll
            for (int i = 0; i < 8; i++)
                #pragma unroll
                for (int j = 0; j < 8; j++)
                    acc[i][j] = fmaf(a[i], b[j], acc[i][j]);
        }
        __syncthreads();
    }

    #pragma unroll
    for (int i = 0; i < 8; i++) {
        int m = m0 + ty*8 + i;
        int b_ = m >> 10, row = m & 1023;
        #pragma unroll
        for (int jc = 0; jc < 2; jc++) {
            int n = n0 + tx*8 + jc*4;
            int h_ = n >> 6, dd = n & 63;
            float4 v = make_float4(acc[i][jc*4], acc[i][jc*4+1],
                                   acc[i][jc*4+2], acc[i][jc*4+3]);
            *(float4*)(Y + ((size_t)(b_*NH + h_) << 16) + (row << 6) + dd) = v;
        }
    }
}

// ---------------------------------------------------------------------------
// Projection GEMM: out = A @ Wp^T (A = g_ao in (B,N,D) layout)
// ---------------------------------------------------------------------------
__global__ void __launch_bounds__(256) gemm_proj(
    const float* __restrict__ W,
    float* __restrict__ Y)
{
    __shared__ float AsT[16][128];
    __shared__ float BsT[16][128];

    int tid = threadIdx.x;
    int tx = tid & 15, ty = tid >> 4;
    int m0 = blockIdx.x * 128, n0 = blockIdx.y * 128;

    float acc[8][8] = {};

    for (int k0 = 0; k0 < DIM; k0 += 16) {
        #pragma unroll
        for (int u = 0; u < 2; u++) {
            int idx = u*256 + tid;
            int m = idx >> 2, kc = (idx & 3) << 2;
            float4 va = *(const float4*)(g_ao + (size_t)(m0+m)*DIM + k0 + kc);
            AsT[kc  ][m] = va.x; AsT[kc+1][m] = va.y;
            AsT[kc+2][m] = va.z; AsT[kc+3][m] = va.w;
            float4 vb = *(const float4*)(W + (size_t)(n0+m)*DIM + k0 + kc);
            BsT[kc  ][m] = vb.x; BsT[kc+1][m] = vb.y;
            BsT[kc+2][m] = vb.z; BsT[kc+3][m] = vb.w;
        }
        __syncthreads();
        #pragma unroll
        for (int kk = 0; kk < 16; kk++) {
            float a[8], b[8];
            *(float4*)(a  ) = *(const float4*)&AsT[kk][ty*8];
            *(float4*)(a+4) = *(const float4*)&AsT[kk][ty*8+4];
            *(float4*)(b  ) = *(const float4*)&BsT[kk][tx*8];
            *(float4*)(b+4) = *(const float4*)&BsT[kk][tx*8+4];
            #pragma unroll
            for (int i = 0; i < 8; i++)
                #pragma unroll
                for (int j = 0; j < 8; j++)
                    acc[i][j] = fmaf(a[i], b[j], acc[i][j]);
        }
        __syncthreads();
    }

    #pragma unroll
    for (int i = 0; i < 8; i++) {
        int m = m0 + ty*8 + i;
        #pragma unroll
        for (int jc = 0; jc < 2; jc++) {
            int n = n0 + tx*8 + jc*4;
            float4 v = make_float4(acc[i][jc*4], acc[i][jc*4+1],
                                   acc[i][jc*4+2], acc[i][jc*4+3]);
            *(float4*)(Y + (size_t)m*DIM + n) = v;
        }
    }
}

// ---------------------------------------------------------------------------
// Flash-style attention. Block = 64 query rows of one (b,h).
// Thread (rr = tid>>3, sg = tid&7): rows {rr, rr+32},
//   S columns {sg + 8t : t<8}, output dims {sg*4..+3} U {sg*4+32..+3}.
// SMEM padded stride 68 -> all LDS patterns conflict-free (verified).
// ---------------------------------------------------------------------------
#define PSTR 68
#define ATTN_SMEM (4*64*PSTR*4)

__global__ void __launch_bounds__(256) attn_kernel(
    const float* __restrict__ logit_lambda)
{
    extern __shared__ float sm[];
    float* Qs = sm;
    float* Ks = sm +     64*PSTR;
    float* Vs = sm + 2 * 64*PSTR;
    float* Ps = sm + 3 * 64*PSTR;

    int tid = threadIdx.x;
    int bh = blockIdx.y;
    int q0 = blockIdx.x * 64;
    int b_ = bh / NH, head = bh % NH;

    const float* qb = g_q + ((size_t)bh << 16);
    const float* kb = g_k + ((size_t)bh << 16);
    const float* vb = g_v + ((size_t)bh << 16);

    float lam   = 1.0f / (1.0f + __expf(-logit_lambda[0]));
    float scale = lam * 0.125f;   // lam / sqrt(64)

    // load Q tile (64 x 64)
    #pragma unroll
    for (int u = 0; u < 4; u++) {
        int idx = u*256 + tid;
        int row = idx >> 4, c4 = (idx & 15) << 2;
        *(float4*)&Qs[row*PSTR + c4] = *(const float4*)&qb[((q0+row) << 6) + c4];
    }

    int rr = tid >> 3;   // 0..31
    int sg = tid & 7;    // 0..7

    float m0 = -1e30f, m1 = -1e30f, l0 = 0.f, l1 = 0.f;
    float o0[8], o1[8];
    #pragma unroll
    for (int c = 0; c < 8; c++) { o0[c] = 0.f; o1[c] = 0.f; }

    for (int kt = 0; kt < SEQ/64; kt++) {
        __syncthreads();
        int k0 = kt * 64;
        #pragma unroll
        for (int u = 0; u < 4; u++) {
            int idx = u*256 + tid;
            int row = idx >> 4, c4 = (idx & 15) << 2;
            *(float4*)&Ks[row*PSTR + c4] = *(const float4*)&kb[((k0+row) << 6) + c4];
            *(float4*)&Vs[row*PSTR + c4] = *(const float4*)&vb[((k0+row) << 6) + c4];
            *(float4*)&Ps[row*PSTR + c4] = *(const float4*)&g_pl[(size_t)(q0+row)*SEQ + k0 + c4];
        }
        __syncthreads();

        // ---- S = scale * (Q K^T) + P_tile ----
        float s0[8], s1[8];
        #pragma unroll
        for (int t = 0; t < 8; t++) { s0[t] = 0.f; s1[t] = 0.f; }
        #pragma unroll
        for (int d0 = 0; d0 < DH; d0 += 4) {
            float4 qa = *(const float4*)&Qs[rr*PSTR + d0];
            float4 qc = *(const float4*)&Qs[(rr+32)*PSTR + d0];
            #pragma unroll
            for (int t = 0; t < 8; t++) {
                float4 kv = *(const float4*)&Ks[(sg + 8*t)*PSTR + d0];
                s0[t] += qa.x*kv.x + qa.y*kv.y + qa.z*kv.z + qa.w*kv.w;
                s1[t] += qc.x*kv.x + qc.y*kv.y + qc.z*kv.z + qc.w*kv.w;
            }
        }
        float tm0 = -1e30f, tm1 = -1e30f;
        #pragma unroll
        for (int t = 0; t < 8; t++) {
            int col = sg + 8*t;
            s0[t] = scale*s0[t] + Ps[rr*PSTR + col];
            s1[t] = scale*s1[t] + Ps[(rr+32)*PSTR + col];
            tm0 = fmaxf(tm0, s0[t]);
            tm1 = fmaxf(tm1, s1[t]);
        }
        #pragma unroll
        for (int off = 1; off < 8; off <<= 1) {
            tm0 = fmaxf(tm0, __shfl_xor_sync(0xffffffffu, tm0, off));
            tm1 = fmaxf(tm1, __shfl_xor_sync(0xffffffffu, tm1, off));
        }
        float nm0 = fmaxf(m0, tm0), nm1 = fmaxf(m1, tm1);
        float r0 = __expf(m0 - nm0), r1 = __expf(m1 - nm1);
        float ts0 = 0.f, ts1 = 0.f;
        #pragma unroll
        for (int t = 0; t < 8; t++) {
            float p0 = __expf(s0[t] - nm0);
            float p1 = __expf(s1[t] - nm1);
            ts0 += p0; ts1 += p1;
            int col = sg + 8*t;
            Ps[rr*PSTR + col]      = p0;
            Ps[(rr+32)*PSTR + col] = p1;
        }
        #pragma unroll
        for (int off = 1; off < 8; off <<= 1) {
            ts0 += __shfl_xor_sync(0xffffffffu, ts0, off);
            ts1 += __shfl_xor_sync(0xffffffffu, ts1, off);
        }
        l0 = l0*r0 + ts0;  l1 = l1*r1 + ts1;
        m0 = nm0;          m1 = nm1;
        #pragma unroll
        for (int c = 0; c < 8; c++) { o0[c] *= r0; o1[c] *= r1; }
        __syncthreads();

        // ---- O += P V ----
        #pragma unroll 4
        for (int jj = 0; jj < 64; jj++) {
            float p0 = Ps[rr*PSTR + jj];
            float p1 = Ps[(rr+32)*PSTR + jj];
            float4 va = *(const float4*)&Vs[jj*PSTR + sg*4];
            float4 vc = *(const float4*)&Vs[jj*PSTR + sg*4 + 32];
            o0[0] += p0*va.x; o0[1] += p0*va.y; o0[2] += p0*va.z; o0[3] += p0*va.w;
            o0[4] += p0*vc.x; o0[5] += p0*vc.y; o0[6] += p0*vc.z; o0[7] += p0*vc.w;
            o1[0] += p1*va.x; o1[1] += p1*va.y; o1[2] += p1*va.z; o1[3] += p1*va.w;
            o1[4] += p1*vc.x; o1[5] += p1*vc.y; o1[6] += p1*vc.z; o1[7] += p1*vc.w;
        }
    }

    float i0 = 1.0f / l0, i1 = 1.0f / l1;
    size_t base0 = (size_t)(b_*SEQ + q0 + rr     )*DIM + head*DH;
    size_t base1 = (size_t)(b_*SEQ + q0 + rr + 32)*DIM + head*DH;
    *(float4*)&g_ao[base0 + sg*4]      = make_float4(o0[0]*i0, o0[1]*i0, o0[2]*i0, o0[3]*i0);
    *(float4*)&g_ao[base0 + sg*4 + 32] = make_float4(o0[4]*i0, o0[5]*i0, o0[6]*i0, o0[7]*i0);
    *(float4*)&g_ao[base1 + sg*4]      = make_float4(o1[0]*i1, o1[1]*i1, o1[2]*i1, o1[3]*i1);
    *(float4*)&g_ao[base1 + sg*4 + 32] = make_float4(o1[4]*i1, o1[5]*i1, o1[6]*i1, o1[7]*i1);
}

// ---------------------------------------------------------------------------
extern "C" void kernel_launch(void* const* d_in, const int* in_sizes, int n_in,
                              void* d_out, int out_size)
{
    const float* x  = (const float*)d_in[0];
    const float* Wq = (const float*)d_in[1];
    const float* Wk = (const float*)d_in[2];
    const float* Wv = (const float*)d_in[3];
    const float* Wp = (const float*)d_in[4];
    const float* ll = (const float*)d_in[5];
    const float* ls = (const float*)d_in[6];
    float* out = (float*)d_out;

    cudaFuncSetAttribute(attn_kernel,
                         cudaFuncAttributeMaxDynamicSharedMemorySize, ATTN_SMEM);

    pos_kernel<<<SEQ, 256>>>(ll, ls);
    gemm_qkv<<<dim3(64, 3, 3), 256>>>(x, Wq, Wk, Wv);
    attn_kernel<<<dim3(SEQ/64, BATCH*NH), 256, ATTN_SMEM>>>(ll);
    gemm_proj<<<dim3(64, 3, 1), 256>>>(Wp, out);
}

// round 3
// speedup vs baseline: 1.2009x; 1.2009x over previous
#include <cuda_runtime.h>
#include <cuda_bf16.h>
#include <math.h>
#include <stdint.h>

#define DIM 384
#define NH 6
#define DH 64
#define BATCH 8
#define SEQ 1024
#define MTOT (BATCH*SEQ)

// ---------------- scratch (device globals; no allocation allowed) ----------
__device__ float g_q [BATCH*NH*SEQ*DH];
__device__ float g_k [BATCH*NH*SEQ*DH];
__device__ float g_v [BATCH*NH*SEQ*DH];
__device__ float g_ao[MTOT*DIM];
__device__ float g_pl[SEQ*SEQ];

__device__ __nv_bfloat16 g_xhi [MTOT*DIM];
__device__ __nv_bfloat16 g_xlo [MTOT*DIM];
__device__ __nv_bfloat16 g_aohi[MTOT*DIM];
__device__ __nv_bfloat16 g_aolo[MTOT*DIM];
__device__ __nv_bfloat16 g_whi [4*DIM*DIM];
__device__ __nv_bfloat16 g_wlo [4*DIM*DIM];

// ---------------- helpers ---------------------------------------------------
static __device__ __forceinline__ uint32_t smem_u32(const void* p) {
    return (uint32_t)__cvta_generic_to_shared(p);
}
static __device__ __forceinline__ void ldsm_x4(uint32_t* r, uint32_t addr) {
    asm volatile("ldmatrix.sync.aligned.m8n8.x4.shared.b16 {%0,%1,%2,%3}, [%4];"
                 : "=r"(r[0]), "=r"(r[1]), "=r"(r[2]), "=r"(r[3]) : "r"(addr));
}
static __device__ __forceinline__ void mma_bf16(float* d, const uint32_t* a,
                                                uint32_t b0, uint32_t b1) {
    asm volatile(
        "mma.sync.aligned.m16n8k16.row.col.f32.bf16.bf16.f32 "
        "{%0,%1,%2,%3}, {%4,%5,%6,%7}, {%8,%9}, {%0,%1,%2,%3};"
        : "+f"(d[0]), "+f"(d[1]), "+f"(d[2]), "+f"(d[3])
        : "r"(a[0]), "r"(a[1]), "r"(a[2]), "r"(a[3]), "r"(b0), "r"(b1));
}
static __device__ __forceinline__ void cp_async16(uint32_t dst, const void* src) {
    asm volatile("cp.async.cg.shared.global [%0], [%1], 16;" :: "r"(dst), "l"(src));
}

// ---------------------------------------------------------------------------
// Positional kernel: g_pl[i][j] = (1-lam) * exp(-dist2(i,j) / (2 sigma^2))
// ---------------------------------------------------------------------------
__global__ void pos_kernel(const float* __restrict__ logit_lambda,
                           const float* __restrict__ log_sigma)
{
    float ls  = log_sigma[0];
    float sig = log1pf(expf(ls)) + 1e-6f;
    float inv = 1.0f / (2.0f * sig * sig);
    float lam = 1.0f / (1.0f + expf(-logit_lambda[0]));
    float oml = 1.0f - lam;

    int i = blockIdx.x;
    float yi = (float)(i >> 5), xi = (float)(i & 31);
    for (int j = threadIdx.x; j < SEQ; j += blockDim.x) {
        float yj = (float)(j >> 5), xj = (float)(j & 31);
        float dy = yi - yj, dx = xi - xj;
        g_pl[i*SEQ + j] = oml * __expf(-(dy*dy + dx*dx) * inv);
    }
}

// ---------------------------------------------------------------------------
// fp32 -> (bf16 hi, bf16 lo) split
// ---------------------------------------------------------------------------
__global__ void convert_split(const float* __restrict__ src,
                              __nv_bfloat16* __restrict__ hi,
                              __nv_bfloat16* __restrict__ lo, int n)
{
    int i = blockIdx.x * 256 + threadIdx.x;
    if (i < n) {
        float v = src[i];
        __nv_bfloat16 h = __float2bfloat16(v);
        hi[i] = h;
        lo[i] = __float2bfloat16(v - __bfloat162float(h));
    }
}

// ---------------------------------------------------------------------------
// mma.sync bf16-split GEMM: D[M,N] = A @ B^T,  A = Ahi+Alo, B = Bhi+Blo
// effective K = 3*384 = 1152 (terms AhiBhi, AhiBlo, AloBhi).
// 128x128 CTA tile, 8 warps (2x4), warp tile 64x32, BK=64, cp.async 2-stage.
// mode 0: write (b,h,n,dh) layout into g_q/g_k/g_v per blockIdx.z
// mode 1: write plain [M, DIM] into proj_out
// ---------------------------------------------------------------------------
#define GEMM_SMEM 65536

__global__ void __launch_bounds__(256) tc_gemm(
    const __nv_bfloat16* __restrict__ Ahi,
    const __nv_bfloat16* __restrict__ Alo,
    const __nv_bfloat16* __restrict__ Bhi_all,
    const __nv_bfloat16* __restrict__ Blo_all,
    float* __restrict__ proj_out,
    int mode)
{
    extern __shared__ char smc[];
    uint32_t sb = smem_u32(smc);
    const uint32_t sA[2] = {sb,           sb + 16384u};
    const uint32_t sB[2] = {sb + 32768u,  sb + 49152u};

    int tid = threadIdx.x, lane = tid & 31, wid = tid >> 5;
    int warpM = wid >> 2, warpN = wid & 3;            // 2 x 4
    int m0 = blockIdx.x * 128, n0 = blockIdx.y * 128, mat = blockIdx.z;

    const __nv_bfloat16* Bhi = Bhi_all + (size_t)mat * DIM * DIM;
    const __nv_bfloat16* Blo = Blo_all + (size_t)mat * DIM * DIM;

    float acc[4][4][4];
    #pragma unroll
    for (int i = 0; i < 4; i++)
        #pragma unroll
        for (int j = 0; j < 4; j++)
            #pragma unroll
            for (int k = 0; k < 4; k++) acc[i][j][k] = 0.f;

    // chunk c (0..17): seg = c/6 selects term, kc = c%6 selects 64-col slice
    auto issue_load = [&](int c) {
        int buf = c & 1;
        int seg = c / 6, kc = c - seg * 6, koff = kc * 64;
        const __nv_bfloat16* Ag = (seg == 2) ? Alo : Ahi;
        const __nv_bfloat16* Bg = (seg == 1) ? Blo : Bhi;
        #pragma unroll
        for (int it = 0; it < 4; it++) {
            int idx = it * 256 + tid;
            int row = idx >> 3, cc = idx & 7;
            uint32_t soff = (uint32_t)(row * 128 + ((cc ^ (row & 7)) << 4));
            cp_async16(sA[buf] + soff, Ag + (size_t)(m0 + row) * DIM + koff + cc * 8);
            cp_async16(sB[buf] + soff, Bg + (size_t)(n0 + row) * DIM + koff + cc * 8);
        }
        asm volatile("cp.async.commit_group;" ::: "memory");
    };

    issue_load(0);

    for (int c = 0; c < 18; c++) {
        if (c + 1 < 18) {
            issue_load(c + 1);
            asm volatile("cp.async.wait_group 1;" ::: "memory");
        } else {
            asm volatile("cp.async.wait_group 0;" ::: "memory");
        }
        __syncthreads();
        int buf = c & 1;
        #pragma unroll
        for (int ks = 0; ks < 4; ks++) {
            uint32_t afrag[4][4];
            #pragma unroll
            for (int mt = 0; mt < 4; mt++) {
                int r = warpM * 64 + mt * 16 + (lane & 15);
                int chunk = ((ks * 2 + (lane >> 4)) ^ (r & 7));
                ldsm_x4(afrag[mt], sA[buf] + (uint32_t)(r * 128 + chunk * 16));
            }
            uint32_t bfrag[2][4];
            #pragma unroll
            for (int bt = 0; bt < 2; bt++) {
                int r = warpN * 32 + bt * 16 + (lane & 15);
                int chunk = ((ks * 2 + (lane >> 4)) ^ (r & 7));
                ldsm_x4(bfrag[bt], sB[buf] + (uint32_t)(r * 128 + chunk * 16));
            }
            #pragma unroll
            for (int mt = 0; mt < 4; mt++)
                #pragma unroll
                for (int nt = 0; nt < 4; nt++) {
                    int bt = nt >> 1, j = nt & 1;
                    mma_bf16(acc[mt][nt], afrag[mt], bfrag[bt][j], bfrag[bt][j + 2]);
                }
        }
        __syncthreads();
    }

    // epilogue: registers -> global (float2 per fragment half)
    int grow = m0 + warpM * 64 + (lane >> 2);
    int gcol = n0 + warpN * 32 + (lane & 3) * 2;
    #pragma unroll
    for (int mt = 0; mt < 4; mt++) {
        #pragma unroll
        for (int nt = 0; nt < 4; nt++) {
            int gm = grow + mt * 16;
            int gn = gcol + nt * 8;
            float2 v0 = make_float2(acc[mt][nt][0], acc[mt][nt][1]);
            float2 v1 = make_float2(acc[mt][nt][2], acc[mt][nt][3]);
            if (mode == 0) {
                float* Y = (mat == 0) ? g_q : (mat == 1) ? g_k : g_v;
                int b = gm >> 10, nrow = gm & 1023;
                int h = gn >> 6,  dd = gn & 63;
                size_t base = ((size_t)(b * NH + h) << 16) + dd;
                *(float2*)(Y + base + ((size_t)nrow       << 6)) = v0;
                *(float2*)(Y + base + ((size_t)(nrow + 8) << 6)) = v1;
            } else {
                *(float2*)(proj_out + (size_t)gm       * DIM + gn) = v0;
                *(float2*)(proj_out + (size_t)(gm + 8) * DIM + gn) = v1;
            }
        }
    }
}

// ---------------------------------------------------------------------------
// Flash-style attention (fp32, unchanged this round)
// ---------------------------------------------------------------------------
#define PSTR 68
#define ATTN_SMEM (4*64*PSTR*4)

__global__ void __launch_bounds__(256) attn_kernel(
    const float* __restrict__ logit_lambda)
{
    extern __shared__ float smf[];
    float* Qs = smf;
    float* Ks = smf +     64*PSTR;
    float* Vs = smf + 2 * 64*PSTR;
    float* Ps = smf + 3 * 64*PSTR;

    int tid = threadIdx.x;
    int bh = blockIdx.y;
    int q0 = blockIdx.x * 64;
    int b_ = bh / NH, head = bh % NH;

    const float* qb = g_q + ((size_t)bh << 16);
    const float* kb = g_k + ((size_t)bh << 16);
    const float* vb = g_v + ((size_t)bh << 16);

    float lam   = 1.0f / (1.0f + __expf(-logit_lambda[0]));
    float scale = lam * 0.125f;

    #pragma unroll
    for (int u = 0; u < 4; u++) {
        int idx = u*256 + tid;
        int row = idx >> 4, c4 = (idx & 15) << 2;
        *(float4*)&Qs[row*PSTR + c4] = *(const float4*)&qb[((q0+row) << 6) + c4];
    }

    int rr = tid >> 3;
    int sg = tid & 7;

    float m0 = -1e30f, m1 = -1e30f, l0 = 0.f, l1 = 0.f;
    float o0[8], o1[8];
    #pragma unroll
    for (int c = 0; c < 8; c++) { o0[c] = 0.f; o1[c] = 0.f; }

    for (int kt = 0; kt < SEQ/64; kt++) {
        __syncthreads();
        int k0 = kt * 64;
        #pragma unroll
        for (int u = 0; u < 4; u++) {
            int idx = u*256 + tid;
            int row = idx >> 4, c4 = (idx & 15) << 2;
            *(float4*)&Ks[row*PSTR + c4] = *(const float4*)&kb[((k0+row) << 6) + c4];
            *(float4*)&Vs[row*PSTR + c4] = *(const float4*)&vb[((k0+row) << 6) + c4];
            *(float4*)&Ps[row*PSTR + c4] = *(const float4*)&g_pl[(size_t)(q0+row)*SEQ + k0 + c4];
        }
        __syncthreads();

        float s0[8], s1[8];
        #pragma unroll
        for (int t = 0; t < 8; t++) { s0[t] = 0.f; s1[t] = 0.f; }
        #pragma unroll
        for (int d0 = 0; d0 < DH; d0 += 4) {
            float4 qa = *(const float4*)&Qs[rr*PSTR + d0];
            float4 qc = *(const float4*)&Qs[(rr+32)*PSTR + d0];
            #pragma unroll
            for (int t = 0; t < 8; t++) {
                float4 kv = *(const float4*)&Ks[(sg + 8*t)*PSTR + d0];
                s0[t] += qa.x*kv.x + qa.y*kv.y + qa.z*kv.z + qa.w*kv.w;
                s1[t] += qc.x*kv.x + qc.y*kv.y + qc.z*kv.z + qc.w*kv.w;
            }
        }
        float tm0 = -1e30f, tm1 = -1e30f;
        #pragma unroll
        for (int t = 0; t < 8; t++) {
            int col = sg + 8*t;
            s0[t] = scale*s0[t] + Ps[rr*PSTR + col];
            s1[t] = scale*s1[t] + Ps[(rr+32)*PSTR + col];
            tm0 = fmaxf(tm0, s0[t]);
            tm1 = fmaxf(tm1, s1[t]);
        }
        #pragma unroll
        for (int off = 1; off < 8; off <<= 1) {
            tm0 = fmaxf(tm0, __shfl_xor_sync(0xffffffffu, tm0, off));
            tm1 = fmaxf(tm1, __shfl_xor_sync(0xffffffffu, tm1, off));
        }
        float nm0 = fmaxf(m0, tm0), nm1 = fmaxf(m1, tm1);
        float r0 = __expf(m0 - nm0), r1 = __expf(m1 - nm1);
        float ts0 = 0.f, ts1 = 0.f;
        #pragma unroll
        for (int t = 0; t < 8; t++) {
            float p0 = __expf(s0[t] - nm0);
            float p1 = __expf(s1[t] - nm1);
            ts0 += p0; ts1 += p1;
            int col = sg + 8*t;
            Ps[rr*PSTR + col]      = p0;
            Ps[(rr+32)*PSTR + col] = p1;
        }
        #pragma unroll
        for (int off = 1; off < 8; off <<= 1) {
            ts0 += __shfl_xor_sync(0xffffffffu, ts0, off);
            ts1 += __shfl_xor_sync(0xffffffffu, ts1, off);
        }
        l0 = l0*r0 + ts0;  l1 = l1*r1 + ts1;
        m0 = nm0;          m1 = nm1;
        #pragma unroll
        for (int c = 0; c < 8; c++) { o0[c] *= r0; o1[c] *= r1; }
        __syncthreads();

        #pragma unroll 4
        for (int jj = 0; jj < 64; jj++) {
            float p0 = Ps[rr*PSTR + jj];
            float p1 = Ps[(rr+32)*PSTR + jj];
            float4 va = *(const float4*)&Vs[jj*PSTR + sg*4];
            float4 vc = *(const float4*)&Vs[jj*PSTR + sg*4 + 32];
            o0[0] += p0*va.x; o0[1] += p0*va.y; o0[2] += p0*va.z; o0[3] += p0*va.w;
            o0[4] += p0*vc.x; o0[5] += p0*vc.y; o0[6] += p0*vc.z; o0[7] += p0*vc.w;
            o1[0] += p1*va.x; o1[1] += p1*va.y; o1[2] += p1*va.z; o1[3] += p1*va.w;
            o1[4] += p1*vc.x; o1[5] += p1*vc.y; o1[6] += p1*vc.z; o1[7] += p1*vc.w;
        }
    }

    float i0 = 1.0f / l0, i1 = 1.0f / l1;
    size_t base0 = (size_t)(b_*SEQ + q0 + rr     )*DIM + head*DH;
    size_t base1 = (size_t)(b_*SEQ + q0 + rr + 32)*DIM + head*DH;
    *(float4*)&g_ao[base0 + sg*4]      = make_float4(o0[0]*i0, o0[1]*i0, o0[2]*i0, o0[3]*i0);
    *(float4*)&g_ao[base0 + sg*4 + 32] = make_float4(o0[4]*i0, o0[5]*i0, o0[6]*i0, o0[7]*i0);
    *(float4*)&g_ao[base1 + sg*4]      = make_float4(o1[0]*i1, o1[1]*i1, o1[2]*i1, o1[3]*i1);
    *(float4*)&g_ao[base1 + sg*4 + 32] = make_float4(o1[4]*i1, o1[5]*i1, o1[6]*i1, o1[7]*i1);
}

// ---------------------------------------------------------------------------
extern "C" void kernel_launch(void* const* d_in, const int* in_sizes, int n_in,
                              void* d_out, int out_size)
{
    const float* x  = (const float*)d_in[0];
    const float* Wq = (const float*)d_in[1];
    const float* Wk = (const float*)d_in[2];
    const float* Wv = (const float*)d_in[3];
    const float* Wp = (const float*)d_in[4];
    const float* ll = (const float*)d_in[5];
    const float* ls = (const float*)d_in[6];
    float* out = (float*)d_out;

    cudaFuncSetAttribute(attn_kernel,
                         cudaFuncAttributeMaxDynamicSharedMemorySize, ATTN_SMEM);
    cudaFuncSetAttribute(tc_gemm,
                         cudaFuncAttributeMaxDynamicSharedMemorySize, GEMM_SMEM);

    __nv_bfloat16 *xhi, *xlo, *aohi, *aolo, *whi, *wlo;
    cudaGetSymbolAddress((void**)&xhi,  g_xhi);
    cudaGetSymbolAddress((void**)&xlo,  g_xlo);
    cudaGetSymbolAddress((void**)&aohi, g_aohi);
    cudaGetSymbolAddress((void**)&aolo, g_aolo);
    cudaGetSymbolAddress((void**)&whi,  g_whi);
    cudaGetSymbolAddress((void**)&wlo,  g_wlo);
    float* ao;
    cudaGetSymbolAddress((void**)&ao, g_ao);

    pos_kernel<<<SEQ, 256>>>(ll, ls);

    convert_split<<<(MTOT*DIM + 255)/256, 256>>>(x, xhi, xlo, MTOT*DIM);
    convert_split<<<(DIM*DIM + 255)/256, 256>>>(Wq, whi + 0*DIM*DIM, wlo + 0*DIM*DIM, DIM*DIM);
    convert_split<<<(DIM*DIM + 255)/256, 256>>>(Wk, whi + 1*DIM*DIM, wlo + 1*DIM*DIM, DIM*DIM);
    convert_split<<<(DIM*DIM + 255)/256, 256>>>(Wv, whi + 2*DIM*DIM, wlo + 2*DIM*DIM, DIM*DIM);
    convert_split<<<(DIM*DIM + 255)/256, 256>>>(Wp, whi + 3*DIM*DIM, wlo + 3*DIM*DIM, DIM*DIM);

    tc_gemm<<<dim3(64, 3, 3), 256, GEMM_SMEM>>>(xhi, xlo, whi, wlo, nullptr, 0);

    attn_kernel<<<dim3(SEQ/64, BATCH*NH), 256, ATTN_SMEM>>>(ll);

    convert_split<<<(MTOT*DIM + 255)/256, 256>>>(ao, aohi, aolo, MTOT*DIM);
    tc_gemm<<<dim3(64, 3, 1), 256, GEMM_SMEM>>>(aohi, aolo,
                                                whi + 3*DIM*DIM, wlo + 3*DIM*DIM,
                                                out, 1);
}